// round 1
// baseline (speedup 1.0000x reference)
#include <cuda_runtime.h>
#include <math.h>

#define Bn     32
#define Sn     32
#define BS     1024      // Bn*Sn
#define EMBn   300
#define HIDn   128
#define G4n    512       // 4*HID
#define AUDn   74
#define D1n    16
#define D2n    16
#define DIMn   256       // D1*D2
#define UNITSn 128
#define CELLn  64

// ---------------- scratch (device globals; no allocation) ----------------
__device__ float sc_wihT[EMBn * G4n];        // 300 x 512  (w_ih transposed)
__device__ float sc_whh4[G4n * HIDn];        // packed: [(k4*512+j)*4+c] = w_hh[j][4*k4+c]
__device__ float sc_X[BS * G4n];             // gate pre-activations from input path
__device__ float sc_h[BS * HIDn];            // LSTM hidden states, all timesteps
__device__ float sc_RI[BS * 2 * DIMn];       // [real(256) | imag(256)] per position
__device__ float sc_WT[2 * DIMn * 2 * UNITSn]; // 512 x 256 measurement matrix
__device__ float sc_knInv[UNITSn];
__device__ float sc_weight[BS];
__device__ float sc_PP[BS * 2 * UNITSn];     // [pr(128) | pi(128)] per position

__device__ __forceinline__ float sigm(float x) { return 1.0f / (1.0f + expf(-x)); }

// ---------------- K0a: transpose/pack weights ----------------
__global__ void prep_transpose(const float* __restrict__ w_ih,
                               const float* __restrict__ w_hh) {
    int total = EMBn * G4n + G4n * HIDn;
    for (int idx = blockIdx.x * blockDim.x + threadIdx.x; idx < total;
         idx += gridDim.x * blockDim.x) {
        if (idx < EMBn * G4n) {
            int j = idx & (G4n - 1);
            int k = idx >> 9;
            sc_wihT[idx] = w_ih[j * EMBn + k];
        } else {
            int i = idx - EMBn * G4n;
            int c = i & 3;
            int t = i >> 2;
            int j = t & (G4n - 1);
            int k4 = t >> 9;
            sc_whh4[i] = w_hh[j * HIDn + (k4 << 2) + c];
        }
    }
}

// ---------------- K0b1: measurement-kernel norms ----------------
__global__ void prep_kn(const float* __restrict__ mr, const float* __restrict__ mi) {
    __shared__ float red[64];
    int u = blockIdx.x;
    float s = 0.f;
    for (int d = threadIdx.x; d < DIMn; d += 64) {
        float r = mr[u * DIMn + d], i = mi[u * DIMn + d];
        s += r * r + i * i;
    }
    red[threadIdx.x] = s;
    __syncthreads();
    for (int o = 32; o > 0; o >>= 1) {
        if (threadIdx.x < o) red[threadIdx.x] += red[threadIdx.x + o];
        __syncthreads();
    }
    if (threadIdx.x == 0) sc_knInv[u] = 1.0f / (sqrtf(red[0]) + 1e-10f);
}

// ---------------- K0b2: build 512x256 measurement matrix ----------------
// col c<128: pr_u ;  col c>=128: pi_{c-128}
// pr = vr.real + vi.imag ; pi = vr.imag - vi.real
__global__ void prep_WT(const float* __restrict__ mr, const float* __restrict__ mi) {
    int idx = blockIdx.x * blockDim.x + threadIdx.x; // 512*256 exactly
    int r = idx >> 8;        // 0..511
    int c = idx & 255;       // 0..255
    float v;
    if (r < DIMn) {
        int d = r;
        if (c < UNITSn) v =  mr[c * DIMn + d] * sc_knInv[c];
        else { int u = c - UNITSn; v = -mi[u * DIMn + d] * sc_knInv[u]; }
    } else {
        int d = r - DIMn;
        if (c < UNITSn) v =  mi[c * DIMn + d] * sc_knInv[c];
        else { int u = c - UNITSn; v =  mr[u * DIMn + d] * sc_knInv[u]; }
    }
    sc_WT[idx] = v;
}

// ---------------- K1: X = emb[word] @ w_ih.T + b_ih + b_hh ----------------
// grid (4 gate-tiles, 64 bs-tiles), 256 threads = (2 row-halves x 128 gates)
__global__ void gemm_X(const int* __restrict__ word,
                       const float* __restrict__ lut,
                       const float* __restrict__ b_ih,
                       const float* __restrict__ b_hh) {
    __shared__ float emb[16 * EMBn];
    int bs0 = blockIdx.y * 16;
    for (int i = threadIdx.x; i < 16 * EMBn; i += 256) {
        int r = i / EMBn, k = i - r * EMBn;
        emb[i] = lut[(long)word[bs0 + r] * EMBn + k];
    }
    __syncthreads();
    int half = threadIdx.x >> 7;
    int g = threadIdx.x & 127;
    int j = blockIdx.x * 128 + g;
    float bias = b_ih[j] + b_hh[j];
    float acc[8];
#pragma unroll
    for (int q = 0; q < 8; q++) acc[q] = bias;
    const float* es = emb + half * 8 * EMBn;
    const float* wp = sc_wihT + j;
    for (int k0 = 0; k0 < EMBn; k0 += 4) {
        float4 e[8];
#pragma unroll
        for (int q = 0; q < 8; q++) e[q] = *(const float4*)&es[q * EMBn + k0];
#pragma unroll
        for (int kk = 0; kk < 4; kk++) {
            float w = wp[(k0 + kk) * G4n];
#pragma unroll
            for (int q = 0; q < 8; q++) {
                float ev = (kk == 0) ? e[q].x : (kk == 1) ? e[q].y : (kk == 2) ? e[q].z : e[q].w;
                acc[q] = fmaf(ev, w, acc[q]);
            }
        }
    }
#pragma unroll
    for (int q = 0; q < 8; q++)
        sc_X[(bs0 + half * 8 + q) * G4n + j] = acc[q];
}

// ---------------- K2: LSTM recurrence, one block per batch ----------------
// 512 threads = one per gate. w_hh: first 64 k's from smem (128KB), rest from L1/L2.
__global__ void lstm_kernel() {
    extern __shared__ float4 wsm[];                 // 8192 float4 = 128KB (k4 0..15)
    __shared__ float4 h4[HIDn / 4];
    __shared__ float gates[G4n];
    int b = blockIdx.x;
    int tid = threadIdx.x;
    const float4* wg = (const float4*)sc_whh4;
    for (int i = tid; i < 8192; i += 512) wsm[i] = wg[i];
    if (tid < 32) h4[tid] = make_float4(0.f, 0.f, 0.f, 0.f);
    float c = 0.f;
    __syncthreads();
    for (int t = 0; t < Sn; t++) {
        float acc = sc_X[(b * Sn + t) * G4n + tid];
#pragma unroll
        for (int k4 = 0; k4 < 16; k4++) {
            float4 w = wsm[k4 * 512 + tid];
            float4 h = h4[k4];
            acc = fmaf(w.x, h.x, acc); acc = fmaf(w.y, h.y, acc);
            acc = fmaf(w.z, h.z, acc); acc = fmaf(w.w, h.w, acc);
        }
#pragma unroll
        for (int k4 = 16; k4 < 32; k4++) {
            float4 w = wg[k4 * 512 + tid];
            float4 h = h4[k4];
            acc = fmaf(w.x, h.x, acc); acc = fmaf(w.y, h.y, acc);
            acc = fmaf(w.z, h.z, acc); acc = fmaf(w.w, h.w, acc);
        }
        gates[tid] = acc;
        __syncthreads();
        if (tid < HIDn) {
            float ig = sigm(gates[tid]);
            float fg = sigm(gates[HIDn + tid]);
            float gg = tanhf(gates[2 * HIDn + tid]);
            float og = sigm(gates[3 * HIDn + tid]);
            c = fg * c + ig * gg;
            float h = og * tanhf(c);
            ((float*)h4)[tid] = h;
            sc_h[(b * Sn + t) * HIDn + tid] = h;
        }
        __syncthreads();
    }
}

// ---------------- K3: per-position combine -> real/imag outer product ----------------
__global__ void combine_kernel(const int* __restrict__ word,
                               const float* __restrict__ audio,
                               const float* __restrict__ ph0t,
                               const float* __restrict__ ph1t,
                               const float* __restrict__ w_lin, const float* __restrict__ b_lin,
                               const float* __restrict__ w1, const float* __restrict__ b1,
                               const float* __restrict__ w2, const float* __restrict__ b2,
                               const float* __restrict__ w3, const float* __restrict__ b3,
                               const float* __restrict__ modw) {
    __shared__ float hs[HIDn], a0[AUDn], a1v[D2n], a2v[D2n];
    __shared__ float amp0[D1n], amp1[D2n], tpr[D1n], tpi[D1n], r1[D2n], i1[D2n];
    __shared__ float nrm[2];
    int bs = blockIdx.x;
    int tid = threadIdx.x;
    int w = word[bs];
    hs[tid] = sc_h[bs * HIDn + tid];
    if (tid < AUDn) a0[tid] = audio[bs * AUDn + tid];
    __syncthreads();
    if (tid < D1n) {
        float s = b_lin[tid];
        for (int k = 0; k < HIDn; k++) s = fmaf(hs[k], w_lin[tid * HIDn + k], s);
        amp0[tid] = s;
        float s1 = b1[tid];
        for (int k = 0; k < AUDn; k++) s1 = fmaf(a0[k], w1[tid * AUDn + k], s1);
        a1v[tid] = fmaxf(s1, 0.f);
    }
    __syncthreads();
    if (tid < D2n) {
        float s = b2[tid];
        for (int k = 0; k < D2n; k++) s = fmaf(a1v[k], w2[tid * D2n + k], s);
        a2v[tid] = fmaxf(s, 0.f);
    }
    __syncthreads();
    if (tid < D2n) {
        float s = b3[tid];
        for (int k = 0; k < D2n; k++) s = fmaf(a2v[k], w3[tid * D2n + k], s);
        amp1[tid] = fmaxf(s, 0.f);
    }
    __syncthreads();
    if (tid == 0) {
        float s0 = 0.f, s1 = 0.f;
        for (int d = 0; d < D1n; d++) { s0 += amp0[d] * amp0[d]; s1 += amp1[d] * amp1[d]; }
        float n0 = sqrtf(s0), n1 = sqrtf(s1);
        nrm[0] = n0; nrm[1] = n1;
        float e0 = expf(modw[0]), e1 = expf(modw[1]);
        sc_weight[bs] = (e0 * n0 + e1 * n1) / (e0 + e1);
    }
    __syncthreads();
    if (tid < D1n) {
        int d = tid;
        float an0 = amp0[d] / (nrm[0] + 1e-10f);
        float p0 = ph0t[(long)w * D1n + d];
        float rr = an0 * cosf(p0), ii = an0 * sinf(p0);
        tpr[d] = rr - ii;
        tpi[d] = rr + ii;
        float an1 = amp1[d] / (nrm[1] + 1e-10f);
        float p1 = ph1t[(long)w * D2n + d];
        r1[d] = an1 * cosf(p1);
        i1[d] = an1 * sinf(p1);
    }
    __syncthreads();
    for (int idx = tid; idx < 2 * DIMn; idx += 128) {
        float v;
        if (idx < DIMn) {
            int i = idx >> 4, j = idx & 15;
            v = tpr[i] * r1[j] - tpi[i] * i1[j];
        } else {
            int t2 = idx - DIMn;
            int i = t2 >> 4, j = t2 & 15;
            v = tpr[i] * i1[j] + tpi[i] * r1[j];
        }
        sc_RI[bs * 2 * DIMn + idx] = v;
    }
}

// ---------------- K4: (1024x512) @ WT(512x256) -> [pr|pi] ----------------
// grid (2 col-tiles, 64 row-tiles), 256 threads = (2 row-halves x 128 cols)
__global__ void gemm_M() {
    __shared__ float As[16 * 512];
    int bs0 = blockIdx.y * 16;
    for (int i = threadIdx.x; i < 16 * 512; i += 256)
        As[i] = sc_RI[bs0 * 512 + i];
    __syncthreads();
    int half = threadIdx.x >> 7;
    int c = blockIdx.x * 128 + (threadIdx.x & 127);
    float acc[8];
#pragma unroll
    for (int q = 0; q < 8; q++) acc[q] = 0.f;
    const float* as = As + half * 8 * 512;
    for (int r0 = 0; r0 < 512; r0 += 4) {
        float4 e[8];
#pragma unroll
        for (int q = 0; q < 8; q++) e[q] = *(const float4*)&as[q * 512 + r0];
#pragma unroll
        for (int rr = 0; rr < 4; rr++) {
            float w = sc_WT[(r0 + rr) * 256 + c];
#pragma unroll
            for (int q = 0; q < 8; q++) {
                float ev = (rr == 0) ? e[q].x : (rr == 1) ? e[q].y : (rr == 2) ? e[q].z : e[q].w;
                acc[q] = fmaf(ev, w, acc[q]);
            }
        }
    }
#pragma unroll
    for (int q = 0; q < 8; q++)
        sc_PP[(bs0 + half * 8 + q) * 256 + c] = acc[q];
}

// ---------------- K5: measurement magnitude + windows + max-pool + final MLP ----------------
__global__ void pool_mlp(const float* __restrict__ fw1, const float* __restrict__ fb1,
                         const float* __restrict__ fw2, const float* __restrict__ fb2,
                         const float* __restrict__ fw3, const float* __restrict__ fb3,
                         float* __restrict__ out) {
    __shared__ float Msm[Sn * UNITSn];
    __shared__ float esm[Sn + 2];
    __shared__ float feat[UNITSn], y1[CELLn], y2[CELLn], red[2];
    int b = blockIdx.x;
    int u = threadIdx.x;
    for (int s = 0; s < Sn; s++) {
        float pr = sc_PP[(b * Sn + s) * 256 + u];
        float pi = sc_PP[(b * Sn + s) * 256 + 128 + u];
        Msm[s * UNITSn + u] = pr * pr + pi * pi;
    }
    if (u < Sn) esm[u] = expf(sc_weight[b * Sn + u]);
    if (u >= Sn && u < Sn + 2) esm[u] = 1.0f;   // zero-padded weight -> exp(0)=1
    __syncthreads();
    float f = 0.f;
    for (int s = 0; s < Sn; s++) {
        float m0 = Msm[s * UNITSn + u];
        float m1 = (s + 1 < Sn) ? Msm[(s + 1) * UNITSn + u] : 0.f;
        float m2 = (s + 2 < Sn) ? Msm[(s + 2) * UNITSn + u] : 0.f;
        float e0 = esm[s], e1 = esm[s + 1], e2 = esm[s + 2];
        float p3 = (e0 * m0 + e1 * m1 + e2 * m2) / (e0 + e1 + e2);
        f = fmaxf(f, fmaxf(m0, p3));
    }
    feat[u] = f;
    __syncthreads();
    if (u < CELLn) {
        float s = fb1[u];
        for (int k = 0; k < UNITSn; k++) s = fmaf(feat[k], fw1[u * UNITSn + k], s);
        y1[u] = fmaxf(s, 0.f);
    }
    __syncthreads();
    if (u < CELLn) {
        float s = fb2[u];
        for (int k = 0; k < CELLn; k++) s = fmaf(y1[k], fw2[u * CELLn + k], s);
        y2[u] = fmaxf(s, 0.f);
    }
    __syncthreads();
    if (u < CELLn) {
        float v = y2[u] * fw3[u];
        for (int o = 16; o > 0; o >>= 1) v += __shfl_down_sync(0xffffffff, v, o);
        if ((u & 31) == 0) red[u >> 5] = v;
    }
    __syncthreads();
    if (u == 0) out[b] = red[0] + red[1] + fb3[0];
}

// ---------------- launch ----------------
extern "C" void kernel_launch(void* const* d_in, const int* in_sizes, int n_in,
                              void* d_out, int out_size) {
    const int*   word  = (const int*)  d_in[0];
    const float* audio = (const float*)d_in[1];
    const float* lut   = (const float*)d_in[2];
    const float* ph0   = (const float*)d_in[3];
    const float* ph1   = (const float*)d_in[4];
    const float* w_ih  = (const float*)d_in[5];
    const float* w_hh  = (const float*)d_in[6];
    const float* b_ih  = (const float*)d_in[7];
    const float* b_hh  = (const float*)d_in[8];
    const float* w_lin = (const float*)d_in[9];
    const float* b_lin = (const float*)d_in[10];
    const float* w1    = (const float*)d_in[11];
    const float* b1    = (const float*)d_in[12];
    const float* w2    = (const float*)d_in[13];
    const float* b2    = (const float*)d_in[14];
    const float* w3    = (const float*)d_in[15];
    const float* b3    = (const float*)d_in[16];
    const float* modw  = (const float*)d_in[17];
    const float* mr    = (const float*)d_in[18];
    const float* mi    = (const float*)d_in[19];
    const float* fw1   = (const float*)d_in[20];
    const float* fb1   = (const float*)d_in[21];
    const float* fw2   = (const float*)d_in[22];
    const float* fb2   = (const float*)d_in[23];
    const float* fw3   = (const float*)d_in[24];
    const float* fb3   = (const float*)d_in[25];
    float* out = (float*)d_out;

    cudaFuncSetAttribute(lstm_kernel, cudaFuncAttributeMaxDynamicSharedMemorySize, 131072);

    prep_transpose<<<512, 256>>>(w_ih, w_hh);
    prep_kn<<<128, 64>>>(mr, mi);
    prep_WT<<<512, 256>>>(mr, mi);
    gemm_X<<<dim3(4, 64), 256>>>(word, lut, b_ih, b_hh);
    lstm_kernel<<<32, 512, 131072>>>();
    combine_kernel<<<BS, 128>>>(word, audio, ph0, ph1, w_lin, b_lin,
                                w1, b1, w2, b2, w3, b3, modw);
    gemm_M<<<dim3(2, 64), 256>>>();
    pool_mlp<<<32, 128>>>(fw1, fb1, fw2, fb2, fw3, fb3, out);
}

// round 3
// speedup vs baseline: 1.2046x; 1.2046x over previous
#include <cuda_runtime.h>
#include <math.h>

#define Bn     32
#define Sn     32
#define BS     1024
#define EMBn   300
#define HIDn   128
#define G4n    512
#define AUDn   74
#define D1n    16
#define D2n    16
#define DIMn   256
#define UNITSn 128
#define CELLn  64

typedef unsigned long long u64;

// ---------------- scratch ----------------
__device__ __align__(16) float sc_wihT[EMBn * G4n];     // [k][j] 300x512
__device__ __align__(16) float sc_whh4[G4n * HIDn];     // [(k4*512+j)*4+c] = w_hh[j][4k4+c]
__device__ __align__(16) float sc_X[BS * G4n];
__device__ __align__(16) float sc_h[BS * HIDn];
__device__ __align__(16) float sc_RI[BS * 2 * DIMn];
__device__ __align__(16) float sc_WT[2 * DIMn * 2 * UNITSn];  // 512 x 256
__device__ float sc_weight[BS];
__device__ __align__(16) float sc_PP[BS * 2 * UNITSn];

// ---------------- f32x2 helpers ----------------
__device__ __forceinline__ u64 pk2(float x, float y) {
    u64 r; asm("mov.b64 %0,{%1,%2};" : "=l"(r) : "f"(x), "f"(y)); return r;
}
__device__ __forceinline__ void upk2(float& x, float& y, u64 v) {
    asm("mov.b64 {%0,%1},%2;" : "=f"(x), "=f"(y) : "l"(v));
}
__device__ __forceinline__ void fma2(u64& d, u64 a, u64 b) {
    asm("fma.rn.f32x2 %0,%1,%2,%0;" : "+l"(d) : "l"(a), "l"(b));
}
__device__ __forceinline__ float sigm(float x) { return 1.0f / (1.0f + expf(-x)); }

// ---------------- K0a: transpose/pack weights ----------------
__global__ void prep_transpose(const float* __restrict__ w_ih,
                               const float* __restrict__ w_hh) {
    int total = EMBn * G4n + G4n * HIDn;
    for (int idx = blockIdx.x * blockDim.x + threadIdx.x; idx < total;
         idx += gridDim.x * blockDim.x) {
        if (idx < EMBn * G4n) {
            int j = idx & (G4n - 1);
            int k = idx >> 9;
            sc_wihT[idx] = w_ih[j * EMBn + k];
        } else {
            int i = idx - EMBn * G4n;
            int c = i & 3;
            int t = i >> 2;
            int j = t & (G4n - 1);
            int k4 = t >> 9;
            sc_whh4[i] = w_hh[j * HIDn + (k4 << 2) + c];
        }
    }
}

// ---------------- K0b: norms + measurement matrix in one kernel ----------------
// block = unit u (128 blocks x 256 threads)
__global__ void prep_WT2(const float* __restrict__ mr, const float* __restrict__ mi) {
    __shared__ float red[8];
    __shared__ float sinv;
    int u = blockIdx.x, tid = threadIdx.x;
    float r = mr[u * DIMn + tid], i = mi[u * DIMn + tid];
    float s = r * r + i * i;
    for (int sh = 16; sh; sh >>= 1) s += __shfl_down_sync(0xffffffffu, s, sh);
    if ((tid & 31) == 0) red[tid >> 5] = s;
    __syncthreads();
    if (tid == 0) {
        float t = 0.f;
        for (int k = 0; k < 8; k++) t += red[k];
        sinv = 1.0f / (sqrtf(t) + 1e-10f);
    }
    __syncthreads();
    float inv = sinv;
    sc_WT[tid * 256 + u]                   = r * inv;     // vr -> pr col
    sc_WT[tid * 256 + UNITSn + u]          = -i * inv;    // -vi -> pi col
    sc_WT[(DIMn + tid) * 256 + u]          = i * inv;     // vi -> pr col
    sc_WT[(DIMn + tid) * 256 + UNITSn + u] = r * inv;     // vr -> pi col
}

// ---------------- K1: X = emb[word] @ w_ih.T + b_ih + b_hh ----------------
// Tiled GEMM: block 64 rows x 64 cols, grid (8,16)=128, 128 threads.
// thread = 4 rows x 8 cols (4 col-pairs, f32x2 accumulators)
__global__ void gemm_X(const int* __restrict__ word,
                       const float* __restrict__ lut,
                       const float* __restrict__ b_ih,
                       const float* __restrict__ b_hh) {
    __shared__ float As[64 * 60];
    __shared__ float Bs[60 * 64];
    __shared__ int wd[64];
    int tid = threadIdx.x;
    int j0 = blockIdx.x * 64, bs0 = blockIdx.y * 64;
    int ct = tid & 7, rt = tid >> 3;
    if (tid < 64) wd[tid] = word[bs0 + tid];
    u64 acc[4][4];
#pragma unroll
    for (int q = 0; q < 4; q++)
#pragma unroll
        for (int p = 0; p < 4; p++) acc[q][p] = 0ull;
    int jb = j0 + ct * 8;
    float2 bi[4], bh[4];
#pragma unroll
    for (int p = 0; p < 4; p++) {
        bi[p] = *(const float2*)&b_ih[jb + 2 * p];
        bh[p] = *(const float2*)&b_hh[jb + 2 * p];
    }
    __syncthreads();
    for (int c = 0; c < 5; c++) {
        int kc = c * 60;
        for (int i = tid; i < 960; i += 128) {   // A: 64 rows x 15 float4
            int r = i / 15, kq = i - r * 15;
            *(float4*)&As[r * 60 + kq * 4] =
                *(const float4*)&lut[(long)wd[r] * EMBn + kc + kq * 4];
        }
        for (int i = tid; i < 960; i += 128) {   // B: 60 rows x 16 float4
            int r = i >> 4, cq = i & 15;
            *(float4*)&Bs[r * 64 + cq * 4] =
                *(const float4*)&sc_wihT[(kc + r) * G4n + j0 + cq * 4];
        }
        __syncthreads();
#pragma unroll 5
        for (int kk = 0; kk < 60; kk += 4) {
            float4 a0 = *(const float4*)&As[(rt * 4 + 0) * 60 + kk];
            float4 a1 = *(const float4*)&As[(rt * 4 + 1) * 60 + kk];
            float4 a2 = *(const float4*)&As[(rt * 4 + 2) * 60 + kk];
            float4 a3 = *(const float4*)&As[(rt * 4 + 3) * 60 + kk];
#define XDOT(T, E0, E1, E2, E3) { \
            const u64* bp = (const u64*)&Bs[(kk + T) * 64 + ct * 8]; \
            u64 w0 = bp[0], w1 = bp[1], w2 = bp[2], w3 = bp[3]; \
            u64 e; \
            e = pk2(E0, E0); fma2(acc[0][0], e, w0); fma2(acc[0][1], e, w1); fma2(acc[0][2], e, w2); fma2(acc[0][3], e, w3); \
            e = pk2(E1, E1); fma2(acc[1][0], e, w0); fma2(acc[1][1], e, w1); fma2(acc[1][2], e, w2); fma2(acc[1][3], e, w3); \
            e = pk2(E2, E2); fma2(acc[2][0], e, w0); fma2(acc[2][1], e, w1); fma2(acc[2][2], e, w2); fma2(acc[2][3], e, w3); \
            e = pk2(E3, E3); fma2(acc[3][0], e, w0); fma2(acc[3][1], e, w1); fma2(acc[3][2], e, w2); fma2(acc[3][3], e, w3); }
            XDOT(0, a0.x, a1.x, a2.x, a3.x)
            XDOT(1, a0.y, a1.y, a2.y, a3.y)
            XDOT(2, a0.z, a1.z, a2.z, a3.z)
            XDOT(3, a0.w, a1.w, a2.w, a3.w)
#undef XDOT
        }
        __syncthreads();
    }
#pragma unroll
    for (int q = 0; q < 4; q++) {
        int row = bs0 + rt * 4 + q;
#pragma unroll
        for (int p = 0; p < 4; p++) {
            float lo, hi; upk2(lo, hi, acc[q][p]);
            *(float2*)&sc_X[row * G4n + jb + 2 * p] =
                make_float2(lo + bi[p].x + bh[p].x, hi + bi[p].y + bh[p].y);
        }
    }
}

// ---------------- K2: LSTM recurrence, f32x2 inner, one block per batch ----------------
__global__ void lstm_kernel() {
    extern __shared__ ulonglong2 wsm[];            // 16 k4 x 512 gates = 128KB
    __shared__ ulonglong2 h4u[32];
    __shared__ float act[G4n];
    int b = blockIdx.x, tid = threadIdx.x;
    const ulonglong2* wg = (const ulonglong2*)sc_whh4;
    for (int i = tid; i < 16 * 512; i += 512) wsm[i] = wg[i];
    if (tid < 32) { ulonglong2 z; z.x = 0ull; z.y = 0ull; h4u[tid] = z; }
    float c = 0.f;
    __syncthreads();
    for (int t = 0; t < Sn; t++) {
        float x = sc_X[(b * Sn + t) * G4n + tid];
        u64 acc0 = 0ull, acc1 = 0ull;
#pragma unroll
        for (int k4 = 0; k4 < 16; k4++) {
            ulonglong2 wv = wsm[k4 * 512 + tid];
            ulonglong2 hv = h4u[k4];
            fma2(acc0, wv.x, hv.x);
            fma2(acc1, wv.y, hv.y);
        }
#pragma unroll
        for (int k4 = 16; k4 < 32; k4++) {
            ulonglong2 wv = wg[k4 * 512 + tid];
            ulonglong2 hv = h4u[k4];
            fma2(acc0, wv.x, hv.x);
            fma2(acc1, wv.y, hv.y);
        }
        float l0, h0, l1, h1;
        upk2(l0, h0, acc0);
        upk2(l1, h1, acc1);
        float g = x + ((l0 + h0) + (l1 + h1));
        act[tid] = (tid >= 2 * HIDn && tid < 3 * HIDn) ? tanhf(g) : sigm(g);
        __syncthreads();
        if (tid < HIDn) {
            c = act[HIDn + tid] * c + act[tid] * act[2 * HIDn + tid];
            float hh = act[3 * HIDn + tid] * tanhf(c);
            ((float*)h4u)[tid] = hh;
            sc_h[(b * Sn + t) * HIDn + tid] = hh;
        }
        __syncthreads();
    }
}

// ---------------- K3: per-position combine -> real/imag outer product ----------------
__global__ void combine_kernel(const int* __restrict__ word,
                               const float* __restrict__ audio,
                               const float* __restrict__ ph0t,
                               const float* __restrict__ ph1t,
                               const float* __restrict__ w_lin, const float* __restrict__ b_lin,
                               const float* __restrict__ w1, const float* __restrict__ b1,
                               const float* __restrict__ w2, const float* __restrict__ b2,
                               const float* __restrict__ w3, const float* __restrict__ b3,
                               const float* __restrict__ modw) {
    __shared__ float hs[HIDn], a0[80], a1v[D2n], a2v[D2n], amp0[D1n], amp1[D2n];
    __shared__ float tpr[D1n], tpi[D1n], r1s[D2n], i1s[D2n], nrm[2];
    int bs = blockIdx.x, tid = threadIdx.x, lane = tid & 31, warp = tid >> 5;
    int w = word[bs];
    hs[tid] = sc_h[bs * HIDn + tid];
    if (tid < 80) a0[tid] = (tid < AUDn) ? audio[bs * AUDn + tid] : 0.f;
    __syncthreads();
#pragma unroll
    for (int oo = 0; oo < 4; oo++) {
        int o = warp * 4 + oo;
        const float* wl = w_lin + o * HIDn;
        float s = hs[lane] * wl[lane] + hs[lane + 32] * wl[lane + 32]
                + hs[lane + 64] * wl[lane + 64] + hs[lane + 96] * wl[lane + 96];
        for (int sh = 16; sh; sh >>= 1) s += __shfl_down_sync(0xffffffffu, s, sh);
        if (lane == 0) amp0[o] = s + b_lin[o];
        const float* wa = w1 + o * AUDn;
        float t = a0[lane] * wa[lane] + a0[lane + 32] * wa[lane + 32];
        if (lane < AUDn - 64) t += a0[lane + 64] * wa[lane + 64];
        for (int sh = 16; sh; sh >>= 1) t += __shfl_down_sync(0xffffffffu, t, sh);
        if (lane == 0) a1v[o] = fmaxf(t + b1[o], 0.f);
    }
    __syncthreads();
    if (tid < 16) {
        float s = b2[tid];
        for (int k = 0; k < 16; k++) s = fmaf(a1v[k], w2[tid * 16 + k], s);
        a2v[tid] = fmaxf(s, 0.f);
    }
    __syncthreads();
    if (tid < 16) {
        float s = b3[tid];
        for (int k = 0; k < 16; k++) s = fmaf(a2v[k], w3[tid * 16 + k], s);
        amp1[tid] = fmaxf(s, 0.f);
    }
    __syncthreads();
    if (warp == 0) {
        float v = (lane < 16) ? amp0[lane] * amp0[lane] : 0.f;
        for (int sh = 16; sh; sh >>= 1) v += __shfl_down_sync(0xffffffffu, v, sh);
        if (lane == 0) nrm[0] = sqrtf(v);
    }
    if (warp == 1) {
        float v = (lane < 16) ? amp1[lane] * amp1[lane] : 0.f;
        for (int sh = 16; sh; sh >>= 1) v += __shfl_down_sync(0xffffffffu, v, sh);
        if (lane == 0) nrm[1] = sqrtf(v);
    }
    __syncthreads();
    if (tid == 0) {
        float e0 = expf(modw[0]), e1 = expf(modw[1]);
        sc_weight[bs] = (e0 * nrm[0] + e1 * nrm[1]) / (e0 + e1);
    }
    if (tid < 16) {
        float an0 = amp0[tid] / (nrm[0] + 1e-10f);
        float p0 = ph0t[(long)w * D1n + tid];
        float rr = an0 * cosf(p0), ii = an0 * sinf(p0);
        tpr[tid] = rr - ii;
        tpi[tid] = rr + ii;
        float an1 = amp1[tid] / (nrm[1] + 1e-10f);
        float p1 = ph1t[(long)w * D2n + tid];
        r1s[tid] = an1 * cosf(p1);
        i1s[tid] = an1 * sinf(p1);
    }
    __syncthreads();
#pragma unroll
    for (int idx = tid; idx < 2 * DIMn; idx += 128) {
        float v;
        if (idx < DIMn) {
            int i = idx >> 4, j = idx & 15;
            v = tpr[i] * r1s[j] - tpi[i] * i1s[j];
        } else {
            int t2 = idx - DIMn;
            int i = t2 >> 4, j = t2 & 15;
            v = tpr[i] * i1s[j] + tpi[i] * r1s[j];
        }
        sc_RI[bs * 2 * DIMn + idx] = v;
    }
}

// ---------------- K4: (1024x512) @ WT(512x256) -> [pr|pi] ----------------
// block 64 rows x 32 cols, grid (8,16)=128, 128 threads, thread = 4x4 (2 pairs)
__global__ void gemm_M() {
    __shared__ float As[64 * 68];
    __shared__ float Bs[64 * 32];
    int tid = threadIdx.x;
    int j0 = blockIdx.x * 32, bs0 = blockIdx.y * 64;
    int ct = tid & 7, rt = tid >> 3;
    u64 acc[4][2];
#pragma unroll
    for (int q = 0; q < 4; q++) { acc[q][0] = 0ull; acc[q][1] = 0ull; }
    for (int c = 0; c < 8; c++) {
        int kc = c * 64;
        for (int i = tid; i < 1024; i += 128) {
            int r = i >> 4, kq = i & 15;
            *(float4*)&As[r * 68 + kq * 4] =
                *(const float4*)&sc_RI[(bs0 + r) * 512 + kc + kq * 4];
        }
        for (int i = tid; i < 512; i += 128) {
            int r = i >> 3, cq = i & 7;
            *(float4*)&Bs[r * 32 + cq * 4] =
                *(const float4*)&sc_WT[(kc + r) * 256 + j0 + cq * 4];
        }
        __syncthreads();
#pragma unroll 4
        for (int kk = 0; kk < 64; kk += 4) {
            float4 a0 = *(const float4*)&As[(rt * 4 + 0) * 68 + kk];
            float4 a1 = *(const float4*)&As[(rt * 4 + 1) * 68 + kk];
            float4 a2 = *(const float4*)&As[(rt * 4 + 2) * 68 + kk];
            float4 a3 = *(const float4*)&As[(rt * 4 + 3) * 68 + kk];
#define MDOT(T, E0, E1, E2, E3) { \
            const u64* bp = (const u64*)&Bs[(kk + T) * 32 + ct * 4]; \
            u64 w0 = bp[0], w1 = bp[1]; \
            u64 e; \
            e = pk2(E0, E0); fma2(acc[0][0], e, w0); fma2(acc[0][1], e, w1); \
            e = pk2(E1, E1); fma2(acc[1][0], e, w0); fma2(acc[1][1], e, w1); \
            e = pk2(E2, E2); fma2(acc[2][0], e, w0); fma2(acc[2][1], e, w1); \
            e = pk2(E3, E3); fma2(acc[3][0], e, w0); fma2(acc[3][1], e, w1); }
            MDOT(0, a0.x, a1.x, a2.x, a3.x)
            MDOT(1, a0.y, a1.y, a2.y, a3.y)
            MDOT(2, a0.z, a1.z, a2.z, a3.z)
            MDOT(3, a0.w, a1.w, a2.w, a3.w)
#undef MDOT
        }
        __syncthreads();
    }
#pragma unroll
    for (int q = 0; q < 4; q++) {
        int row = bs0 + rt * 4 + q;
#pragma unroll
        for (int p = 0; p < 2; p++) {
            float lo, hi; upk2(lo, hi, acc[q][p]);
            *(float2*)&sc_PP[row * 256 + j0 + ct * 4 + 2 * p] = make_float2(lo, hi);
        }
    }
}

// ---------------- K5: windows + max-pool + final MLP ----------------
__global__ void pool_mlp(const float* __restrict__ fw1, const float* __restrict__ fb1,
                         const float* __restrict__ fw2, const float* __restrict__ fb2,
                         const float* __restrict__ fw3, const float* __restrict__ fb3,
                         float* __restrict__ out) {
    __shared__ float Msm[Sn * UNITSn];
    __shared__ float esm[Sn + 2];
    __shared__ float feat[UNITSn], y1[CELLn], y2[CELLn], red[2];
    int b = blockIdx.x;
    int u = threadIdx.x;
    for (int s = 0; s < Sn; s++) {
        float pr = sc_PP[(b * Sn + s) * 256 + u];
        float pi = sc_PP[(b * Sn + s) * 256 + 128 + u];
        Msm[s * UNITSn + u] = pr * pr + pi * pi;
    }
    if (u < Sn) esm[u] = expf(sc_weight[b * Sn + u]);
    if (u >= Sn && u < Sn + 2) esm[u] = 1.0f;
    __syncthreads();
    float f = 0.f;
    for (int s = 0; s < Sn; s++) {
        float m0 = Msm[s * UNITSn + u];
        float m1 = (s + 1 < Sn) ? Msm[(s + 1) * UNITSn + u] : 0.f;
        float m2 = (s + 2 < Sn) ? Msm[(s + 2) * UNITSn + u] : 0.f;
        float e0 = esm[s], e1 = esm[s + 1], e2 = esm[s + 2];
        float p3 = (e0 * m0 + e1 * m1 + e2 * m2) / (e0 + e1 + e2);
        f = fmaxf(f, fmaxf(m0, p3));
    }
    feat[u] = f;
    __syncthreads();
    if (u < CELLn) {
        float s = fb1[u];
        for (int k = 0; k < UNITSn; k++) s = fmaf(feat[k], fw1[u * UNITSn + k], s);
        y1[u] = fmaxf(s, 0.f);
    }
    __syncthreads();
    if (u < CELLn) {
        float s = fb2[u];
        for (int k = 0; k < CELLn; k++) s = fmaf(y1[k], fw2[u * CELLn + k], s);
        y2[u] = fmaxf(s, 0.f);
    }
    __syncthreads();
    if (u < CELLn) {
        float v = y2[u] * fw3[u];
        for (int o = 16; o > 0; o >>= 1) v += __shfl_down_sync(0xffffffffu, v, o);
        if ((u & 31) == 0) red[u >> 5] = v;
    }
    __syncthreads();
    if (u == 0) out[b] = red[0] + red[1] + fb3[0];
}

// ---------------- launch ----------------
extern "C" void kernel_launch(void* const* d_in, const int* in_sizes, int n_in,
                              void* d_out, int out_size) {
    const int*   word  = (const int*)  d_in[0];
    const float* audio = (const float*)d_in[1];
    const float* lut   = (const float*)d_in[2];
    const float* ph0   = (const float*)d_in[3];
    const float* ph1   = (const float*)d_in[4];
    const float* w_ih  = (const float*)d_in[5];
    const float* w_hh  = (const float*)d_in[6];
    const float* b_ih  = (const float*)d_in[7];
    const float* b_hh  = (const float*)d_in[8];
    const float* w_lin = (const float*)d_in[9];
    const float* b_lin = (const float*)d_in[10];
    const float* w1    = (const float*)d_in[11];
    const float* b1    = (const float*)d_in[12];
    const float* w2    = (const float*)d_in[13];
    const float* b2    = (const float*)d_in[14];
    const float* w3    = (const float*)d_in[15];
    const float* b3    = (const float*)d_in[16];
    const float* modw  = (const float*)d_in[17];
    const float* mr    = (const float*)d_in[18];
    const float* mi    = (const float*)d_in[19];
    const float* fw1   = (const float*)d_in[20];
    const float* fb1   = (const float*)d_in[21];
    const float* fw2   = (const float*)d_in[22];
    const float* fb2   = (const float*)d_in[23];
    const float* fw3   = (const float*)d_in[24];
    const float* fb3   = (const float*)d_in[25];
    float* out = (float*)d_out;

    cudaFuncSetAttribute(lstm_kernel, cudaFuncAttributeMaxDynamicSharedMemorySize, 131072);

    prep_transpose<<<512, 256>>>(w_ih, w_hh);
    prep_WT2<<<128, 256>>>(mr, mi);
    gemm_X<<<dim3(8, 16), 128>>>(word, lut, b_ih, b_hh);
    lstm_kernel<<<32, 512, 131072>>>();
    combine_kernel<<<BS, 128>>>(word, audio, ph0, ph1, w_lin, b_lin,
                                w1, b1, w2, b2, w3, b3, modw);
    gemm_M<<<dim3(8, 16), 128>>>();
    pool_mlp<<<32, 128>>>(fw1, fb1, fw2, fb2, fw3, fb3, out);
}

// round 4
// speedup vs baseline: 1.6047x; 1.3322x over previous
#include <cuda_runtime.h>
#include <math.h>

#define Bn     32
#define Sn     32
#define BS     1024
#define EMBn   300
#define HIDn   128
#define G4n    512
#define AUDn   74
#define D1n    16
#define D2n    16
#define DIMn   256
#define UNITSn 128
#define CELLn  64

typedef unsigned long long u64;

// ---------------- scratch ----------------
__device__ __align__(16) float sc_wihT[EMBn * G4n];     // [k][j] 300x512
__device__ __align__(16) float sc_X[BS * G4n];
__device__ __align__(16) float sc_h[BS * HIDn];
__device__ __align__(16) float sc_RI[BS * 2 * DIMn];
__device__ __align__(16) float sc_WT[2 * DIMn * 2 * UNITSn];  // 512 x 256
__device__ float sc_weight[BS];
__device__ __align__(16) float sc_PP[BS * 2 * UNITSn];

// ---------------- f32x2 / ptx helpers ----------------
__device__ __forceinline__ u64 pk2(float x, float y) {
    u64 r; asm("mov.b64 %0,{%1,%2};" : "=l"(r) : "f"(x), "f"(y)); return r;
}
__device__ __forceinline__ void upk2(float& x, float& y, u64 v) {
    asm("mov.b64 {%0,%1},%2;" : "=f"(x), "=f"(y) : "l"(v));
}
__device__ __forceinline__ void fma2(u64& d, u64 a, u64 b) {
    asm("fma.rn.f32x2 %0,%1,%2,%0;" : "+l"(d) : "l"(a), "l"(b));
}
__device__ __forceinline__ float sigm(float x) { return 1.0f / (1.0f + expf(-x)); }
__device__ __forceinline__ unsigned s2u(const void* p) {
    return (unsigned)__cvta_generic_to_shared(p);
}
__device__ __forceinline__ unsigned mapa32(unsigned a, unsigned r) {
    unsigned d; asm("mapa.shared::cluster.u32 %0,%1,%2;" : "=r"(d) : "r"(a), "r"(r));
    return d;
}
__device__ __forceinline__ void mbar_init(unsigned a, unsigned cnt) {
    asm volatile("mbarrier.init.shared.b64 [%0], %1;" :: "r"(a), "r"(cnt) : "memory");
}
__device__ __forceinline__ void mbar_arrive_remote(unsigned a) {
    asm volatile("mbarrier.arrive.release.cluster.shared::cluster.b64 _, [%0];"
                 :: "r"(a) : "memory");
}
__device__ __forceinline__ void st_remote_f32(unsigned a, float v) {
    asm volatile("st.shared::cluster.f32 [%0], %1;" :: "r"(a), "f"(v) : "memory");
}
__device__ __forceinline__ void mbar_waitc(unsigned a, unsigned parity) {
    asm volatile(
        "{\n\t.reg .pred P;\n"
        "WL%=:\n\t"
        "mbarrier.try_wait.parity.acquire.cluster.shared::cta.b64 P, [%0], %1;\n\t"
        "@P bra WD%=;\n\t"
        "bra WL%=;\n"
        "WD%=:\n\t}"
        :: "r"(a), "r"(parity) : "memory");
}

// ---------------- K0a: transpose w_ih only ----------------
__global__ void prep_transpose(const float* __restrict__ w_ih) {
    int total = EMBn * G4n;
    for (int idx = blockIdx.x * blockDim.x + threadIdx.x; idx < total;
         idx += gridDim.x * blockDim.x) {
        int j = idx & (G4n - 1);
        int k = idx >> 9;
        sc_wihT[idx] = w_ih[j * EMBn + k];
    }
}

// ---------------- K0b: norms + measurement matrix ----------------
__global__ void prep_WT2(const float* __restrict__ mr, const float* __restrict__ mi) {
    __shared__ float red[8];
    __shared__ float sinv;
    int u = blockIdx.x, tid = threadIdx.x;
    float r = mr[u * DIMn + tid], i = mi[u * DIMn + tid];
    float s = r * r + i * i;
    for (int sh = 16; sh; sh >>= 1) s += __shfl_down_sync(0xffffffffu, s, sh);
    if ((tid & 31) == 0) red[tid >> 5] = s;
    __syncthreads();
    if (tid == 0) {
        float t = 0.f;
        for (int k = 0; k < 8; k++) t += red[k];
        sinv = 1.0f / (sqrtf(t) + 1e-10f);
    }
    __syncthreads();
    float inv = sinv;
    sc_WT[tid * 256 + u]                   = r * inv;
    sc_WT[tid * 256 + UNITSn + u]          = -i * inv;
    sc_WT[(DIMn + tid) * 256 + u]          = i * inv;
    sc_WT[(DIMn + tid) * 256 + UNITSn + u] = r * inv;
}

// ---------------- K1: X = emb[word] @ w_ih.T + b_ih + b_hh ----------------
__global__ void gemm_X(const int* __restrict__ word,
                       const float* __restrict__ lut,
                       const float* __restrict__ b_ih,
                       const float* __restrict__ b_hh) {
    __shared__ float As[64 * 60];
    __shared__ float Bs[60 * 64];
    __shared__ int wd[64];
    int tid = threadIdx.x;
    int j0 = blockIdx.x * 64, bs0 = blockIdx.y * 64;
    int ct = tid & 7, rt = tid >> 3;
    if (tid < 64) wd[tid] = word[bs0 + tid];
    u64 acc[4][4];
#pragma unroll
    for (int q = 0; q < 4; q++)
#pragma unroll
        for (int p = 0; p < 4; p++) acc[q][p] = 0ull;
    int jb = j0 + ct * 8;
    float2 bi[4], bh[4];
#pragma unroll
    for (int p = 0; p < 4; p++) {
        bi[p] = *(const float2*)&b_ih[jb + 2 * p];
        bh[p] = *(const float2*)&b_hh[jb + 2 * p];
    }
    __syncthreads();
    for (int c = 0; c < 5; c++) {
        int kc = c * 60;
        for (int i = tid; i < 960; i += 128) {
            int r = i / 15, kq = i - r * 15;
            *(float4*)&As[r * 60 + kq * 4] =
                *(const float4*)&lut[(long)wd[r] * EMBn + kc + kq * 4];
        }
        for (int i = tid; i < 960; i += 128) {
            int r = i >> 4, cq = i & 15;
            *(float4*)&Bs[r * 64 + cq * 4] =
                *(const float4*)&sc_wihT[(kc + r) * G4n + j0 + cq * 4];
        }
        __syncthreads();
#pragma unroll 5
        for (int kk = 0; kk < 60; kk += 4) {
            float4 a0 = *(const float4*)&As[(rt * 4 + 0) * 60 + kk];
            float4 a1 = *(const float4*)&As[(rt * 4 + 1) * 60 + kk];
            float4 a2 = *(const float4*)&As[(rt * 4 + 2) * 60 + kk];
            float4 a3 = *(const float4*)&As[(rt * 4 + 3) * 60 + kk];
#define XDOT(T, E0, E1, E2, E3) { \
            const u64* bp = (const u64*)&Bs[(kk + T) * 64 + ct * 8]; \
            u64 w0 = bp[0], w1 = bp[1], w2 = bp[2], w3 = bp[3]; \
            u64 e; \
            e = pk2(E0, E0); fma2(acc[0][0], e, w0); fma2(acc[0][1], e, w1); fma2(acc[0][2], e, w2); fma2(acc[0][3], e, w3); \
            e = pk2(E1, E1); fma2(acc[1][0], e, w0); fma2(acc[1][1], e, w1); fma2(acc[1][2], e, w2); fma2(acc[1][3], e, w3); \
            e = pk2(E2, E2); fma2(acc[2][0], e, w0); fma2(acc[2][1], e, w1); fma2(acc[2][2], e, w2); fma2(acc[2][3], e, w3); \
            e = pk2(E3, E3); fma2(acc[3][0], e, w0); fma2(acc[3][1], e, w1); fma2(acc[3][2], e, w2); fma2(acc[3][3], e, w3); }
            XDOT(0, a0.x, a1.x, a2.x, a3.x)
            XDOT(1, a0.y, a1.y, a2.y, a3.y)
            XDOT(2, a0.z, a1.z, a2.z, a3.z)
            XDOT(3, a0.w, a1.w, a2.w, a3.w)
#undef XDOT
        }
        __syncthreads();
    }
#pragma unroll
    for (int q = 0; q < 4; q++) {
        int row = bs0 + rt * 4 + q;
#pragma unroll
        for (int p = 0; p < 4; p++) {
            float lo, hi; upk2(lo, hi, acc[q][p]);
            *(float2*)&sc_X[row * G4n + jb + 2 * p] =
                make_float2(lo + bi[p].x + bh[p].x, hi + bi[p].y + bh[p].y);
        }
    }
}

// ---------------- K2: LSTM, weights in registers, 2-CTA cluster per batch ----------------
// grid 64 (cluster 2), 256 threads. CTA rank r owns hidden j in [r*64, r*64+64).
// thread tid = q*64+jj -> gate row q*128 + r*64 + jj; its 128 w_hh weights in regs.
__global__ void __launch_bounds__(256, 1) __cluster_dims__(2, 1, 1)
lstm_kernel(const float* __restrict__ w_hh) {
    __shared__ float Xs[Sn * 256];                 // 32KB prefetch of gate pre-acts
    __shared__ __align__(16) float hbuf[2][HIDn];  // double-buffered h
    __shared__ float act[256];
    __shared__ __align__(8) u64 mbar[2];
    int tid = threadIdx.x;
    int b = blockIdx.x >> 1;
    unsigned rank = blockIdx.x & 1;
    unsigned peer = rank ^ 1;
    int q = tid >> 6, jj = tid & 63;
    int grow = q * 128 + (int)rank * 64 + jj;

    // prefetch X pre-activations for this batch's gate rows
    for (int t = 0; t < Sn; t++)
        Xs[t * 256 + tid] = sc_X[(b * Sn + t) * G4n + grow];
    if (tid < HIDn) hbuf[0][tid] = 0.f;
    unsigned mb0 = s2u(&mbar[0]);
    if (tid == 0) { mbar_init(mb0, 64); mbar_init(mb0 + 8, 64); }

    // weights into registers (64 packed f32x2)
    u64 w2[64];
    const float4* wrow = (const float4*)(w_hh + (long)grow * HIDn);
#pragma unroll
    for (int k = 0; k < 32; k++) {
        float4 v = wrow[k];
        w2[2 * k]     = pk2(v.x, v.y);
        w2[2 * k + 1] = pk2(v.z, v.w);
    }
    __syncthreads();
    asm volatile("barrier.cluster.arrive.aligned;" ::: "memory");
    asm volatile("barrier.cluster.wait.aligned;" ::: "memory");

    unsigned peer_h  = mapa32(s2u(&hbuf[0][0]), peer);
    unsigned peer_mb = mapa32(mb0, peer);
    float c = 0.f;

    for (int t = 0; t < Sn; t++) {
        int cur = t & 1;
        if (t > 0) mbar_waitc(mb0 + cur * 8, ((unsigned)(t - 1) >> 1) & 1);
        const ulonglong2* hp = (const ulonglong2*)hbuf[cur];
        u64 a0 = 0ull, a1 = 0ull;
#pragma unroll
        for (int k = 0; k < 32; k++) {
            ulonglong2 hv = hp[k];
            fma2(a0, w2[2 * k], hv.x);
            fma2(a1, w2[2 * k + 1], hv.y);
        }
        float l0, h0, l1, h1;
        upk2(l0, h0, a0);
        upk2(l1, h1, a1);
        float g = Xs[t * 256 + tid] + ((l0 + h0) + (l1 + h1));
        act[tid] = (q == 2) ? tanhf(g) : sigm(g);
        __syncthreads();
        if (tid < 64) {
            c = act[64 + tid] * c + act[tid] * act[128 + tid];
            float hh = act[192 + tid] * tanhf(c);
            int nxt = (t + 1) & 1;
            int hidx = (int)rank * 64 + tid;
            hbuf[nxt][hidx] = hh;
            sc_h[(b * Sn + t) * HIDn + hidx] = hh;
            if (t < Sn - 1) {
                st_remote_f32(peer_h + (unsigned)(nxt * HIDn + hidx) * 4u, hh);
                mbar_arrive_remote(peer_mb + (unsigned)nxt * 8u);
            }
        }
        __syncthreads();
    }
}

// ---------------- K3: per-position combine -> real/imag outer product ----------------
__global__ void combine_kernel(const int* __restrict__ word,
                               const float* __restrict__ audio,
                               const float* __restrict__ ph0t,
                               const float* __restrict__ ph1t,
                               const float* __restrict__ w_lin, const float* __restrict__ b_lin,
                               const float* __restrict__ w1, const float* __restrict__ b1,
                               const float* __restrict__ w2, const float* __restrict__ b2,
                               const float* __restrict__ w3, const float* __restrict__ b3,
                               const float* __restrict__ modw) {
    __shared__ float hs[HIDn], a0[80], a1v[D2n], a2v[D2n], amp0[D1n], amp1[D2n];
    __shared__ float tpr[D1n], tpi[D1n], r1s[D2n], i1s[D2n], nrm[2];
    int bs = blockIdx.x, tid = threadIdx.x, lane = tid & 31, warp = tid >> 5;
    int w = word[bs];
    hs[tid] = sc_h[bs * HIDn + tid];
    if (tid < 80) a0[tid] = (tid < AUDn) ? audio[bs * AUDn + tid] : 0.f;
    __syncthreads();
#pragma unroll
    for (int oo = 0; oo < 4; oo++) {
        int o = warp * 4 + oo;
        const float* wl = w_lin + o * HIDn;
        float s = hs[lane] * wl[lane] + hs[lane + 32] * wl[lane + 32]
                + hs[lane + 64] * wl[lane + 64] + hs[lane + 96] * wl[lane + 96];
        for (int sh = 16; sh; sh >>= 1) s += __shfl_down_sync(0xffffffffu, s, sh);
        if (lane == 0) amp0[o] = s + b_lin[o];
        const float* wa = w1 + o * AUDn;
        float t = a0[lane] * wa[lane] + a0[lane + 32] * wa[lane + 32];
        if (lane < AUDn - 64) t += a0[lane + 64] * wa[lane + 64];
        for (int sh = 16; sh; sh >>= 1) t += __shfl_down_sync(0xffffffffu, t, sh);
        if (lane == 0) a1v[o] = fmaxf(t + b1[o], 0.f);
    }
    __syncthreads();
    if (tid < 16) {
        float s = b2[tid];
        for (int k = 0; k < 16; k++) s = fmaf(a1v[k], w2[tid * 16 + k], s);
        a2v[tid] = fmaxf(s, 0.f);
    }
    __syncthreads();
    if (tid < 16) {
        float s = b3[tid];
        for (int k = 0; k < 16; k++) s = fmaf(a2v[k], w3[tid * 16 + k], s);
        amp1[tid] = fmaxf(s, 0.f);
    }
    __syncthreads();
    if (warp == 0) {
        float v = (lane < 16) ? amp0[lane] * amp0[lane] : 0.f;
        for (int sh = 16; sh; sh >>= 1) v += __shfl_down_sync(0xffffffffu, v, sh);
        if (lane == 0) nrm[0] = sqrtf(v);
    }
    if (warp == 1) {
        float v = (lane < 16) ? amp1[lane] * amp1[lane] : 0.f;
        for (int sh = 16; sh; sh >>= 1) v += __shfl_down_sync(0xffffffffu, v, sh);
        if (lane == 0) nrm[1] = sqrtf(v);
    }
    __syncthreads();
    if (tid == 0) {
        float e0 = expf(modw[0]), e1 = expf(modw[1]);
        sc_weight[bs] = (e0 * nrm[0] + e1 * nrm[1]) / (e0 + e1);
    }
    if (tid < 16) {
        float an0 = amp0[tid] / (nrm[0] + 1e-10f);
        float p0 = ph0t[(long)w * D1n + tid];
        float rr = an0 * cosf(p0), ii = an0 * sinf(p0);
        tpr[tid] = rr - ii;
        tpi[tid] = rr + ii;
        float an1 = amp1[tid] / (nrm[1] + 1e-10f);
        float p1 = ph1t[(long)w * D2n + tid];
        r1s[tid] = an1 * cosf(p1);
        i1s[tid] = an1 * sinf(p1);
    }
    __syncthreads();
#pragma unroll
    for (int idx = tid; idx < 2 * DIMn; idx += 128) {
        float v;
        if (idx < DIMn) {
            int i = idx >> 4, j = idx & 15;
            v = tpr[i] * r1s[j] - tpi[i] * i1s[j];
        } else {
            int t2 = idx - DIMn;
            int i = t2 >> 4, j = t2 & 15;
            v = tpr[i] * i1s[j] + tpi[i] * r1s[j];
        }
        sc_RI[bs * 2 * DIMn + idx] = v;
    }
}

// ---------------- K4: (1024x512) @ WT(512x256) -> [pr|pi] ----------------
__global__ void gemm_M() {
    __shared__ float As[64 * 68];
    __shared__ float Bs[64 * 32];
    int tid = threadIdx.x;
    int j0 = blockIdx.x * 32, bs0 = blockIdx.y * 64;
    int ct = tid & 7, rt = tid >> 3;
    u64 acc[4][2];
#pragma unroll
    for (int q = 0; q < 4; q++) { acc[q][0] = 0ull; acc[q][1] = 0ull; }
    for (int c = 0; c < 8; c++) {
        int kc = c * 64;
        for (int i = tid; i < 1024; i += 128) {
            int r = i >> 4, kq = i & 15;
            *(float4*)&As[r * 68 + kq * 4] =
                *(const float4*)&sc_RI[(bs0 + r) * 512 + kc + kq * 4];
        }
        for (int i = tid; i < 512; i += 128) {
            int r = i >> 3, cq = i & 7;
            *(float4*)&Bs[r * 32 + cq * 4] =
                *(const float4*)&sc_WT[(kc + r) * 256 + j0 + cq * 4];
        }
        __syncthreads();
#pragma unroll 4
        for (int kk = 0; kk < 64; kk += 4) {
            float4 a0 = *(const float4*)&As[(rt * 4 + 0) * 68 + kk];
            float4 a1 = *(const float4*)&As[(rt * 4 + 1) * 68 + kk];
            float4 a2 = *(const float4*)&As[(rt * 4 + 2) * 68 + kk];
            float4 a3 = *(const float4*)&As[(rt * 4 + 3) * 68 + kk];
#define MDOT(T, E0, E1, E2, E3) { \
            const u64* bp = (const u64*)&Bs[(kk + T) * 32 + ct * 4]; \
            u64 w0 = bp[0], w1 = bp[1]; \
            u64 e; \
            e = pk2(E0, E0); fma2(acc[0][0], e, w0); fma2(acc[0][1], e, w1); \
            e = pk2(E1, E1); fma2(acc[1][0], e, w0); fma2(acc[1][1], e, w1); \
            e = pk2(E2, E2); fma2(acc[2][0], e, w0); fma2(acc[2][1], e, w1); \
            e = pk2(E3, E3); fma2(acc[3][0], e, w0); fma2(acc[3][1], e, w1); }
            MDOT(0, a0.x, a1.x, a2.x, a3.x)
            MDOT(1, a0.y, a1.y, a2.y, a3.y)
            MDOT(2, a0.z, a1.z, a2.z, a3.z)
            MDOT(3, a0.w, a1.w, a2.w, a3.w)
#undef MDOT
        }
        __syncthreads();
    }
#pragma unroll
    for (int q = 0; q < 4; q++) {
        int row = bs0 + rt * 4 + q;
#pragma unroll
        for (int p = 0; p < 2; p++) {
            float lo, hi; upk2(lo, hi, acc[q][p]);
            *(float2*)&sc_PP[row * 256 + j0 + ct * 4 + 2 * p] = make_float2(lo, hi);
        }
    }
}

// ---------------- K5: windows + max-pool + final MLP ----------------
__global__ void pool_mlp(const float* __restrict__ fw1, const float* __restrict__ fb1,
                         const float* __restrict__ fw2, const float* __restrict__ fb2,
                         const float* __restrict__ fw3, const float* __restrict__ fb3,
                         float* __restrict__ out) {
    __shared__ float Msm[Sn * UNITSn];
    __shared__ float esm[Sn + 2];
    __shared__ float feat[UNITSn], y1[CELLn], y2[CELLn], red[2];
    int b = blockIdx.x;
    int u = threadIdx.x;
    for (int s = 0; s < Sn; s++) {
        float pr = sc_PP[(b * Sn + s) * 256 + u];
        float pi = sc_PP[(b * Sn + s) * 256 + 128 + u];
        Msm[s * UNITSn + u] = pr * pr + pi * pi;
    }
    if (u < Sn) esm[u] = expf(sc_weight[b * Sn + u]);
    if (u >= Sn && u < Sn + 2) esm[u] = 1.0f;
    __syncthreads();
    float f = 0.f;
    for (int s = 0; s < Sn; s++) {
        float m0 = Msm[s * UNITSn + u];
        float m1 = (s + 1 < Sn) ? Msm[(s + 1) * UNITSn + u] : 0.f;
        float m2 = (s + 2 < Sn) ? Msm[(s + 2) * UNITSn + u] : 0.f;
        float e0 = esm[s], e1 = esm[s + 1], e2 = esm[s + 2];
        float p3 = (e0 * m0 + e1 * m1 + e2 * m2) / (e0 + e1 + e2);
        f = fmaxf(f, fmaxf(m0, p3));
    }
    feat[u] = f;
    __syncthreads();
    if (u < CELLn) {
        float s = fb1[u];
        for (int k = 0; k < UNITSn; k++) s = fmaf(feat[k], fw1[u * UNITSn + k], s);
        y1[u] = fmaxf(s, 0.f);
    }
    __syncthreads();
    if (u < CELLn) {
        float s = fb2[u];
        for (int k = 0; k < CELLn; k++) s = fmaf(y1[k], fw2[u * CELLn + k], s);
        y2[u] = fmaxf(s, 0.f);
    }
    __syncthreads();
    if (u < CELLn) {
        float v = y2[u] * fw3[u];
        for (int o = 16; o > 0; o >>= 1) v += __shfl_down_sync(0xffffffffu, v, o);
        if ((u & 31) == 0) red[u >> 5] = v;
    }
    __syncthreads();
    if (u == 0) out[b] = red[0] + red[1] + fb3[0];
}

// ---------------- launch ----------------
extern "C" void kernel_launch(void* const* d_in, const int* in_sizes, int n_in,
                              void* d_out, int out_size) {
    const int*   word  = (const int*)  d_in[0];
    const float* audio = (const float*)d_in[1];
    const float* lut   = (const float*)d_in[2];
    const float* ph0   = (const float*)d_in[3];
    const float* ph1   = (const float*)d_in[4];
    const float* w_ih  = (const float*)d_in[5];
    const float* w_hh  = (const float*)d_in[6];
    const float* b_ih  = (const float*)d_in[7];
    const float* b_hh  = (const float*)d_in[8];
    const float* w_lin = (const float*)d_in[9];
    const float* b_lin = (const float*)d_in[10];
    const float* w1    = (const float*)d_in[11];
    const float* b1    = (const float*)d_in[12];
    const float* w2    = (const float*)d_in[13];
    const float* b2    = (const float*)d_in[14];
    const float* w3    = (const float*)d_in[15];
    const float* b3    = (const float*)d_in[16];
    const float* modw  = (const float*)d_in[17];
    const float* mr    = (const float*)d_in[18];
    const float* mi    = (const float*)d_in[19];
    const float* fw1   = (const float*)d_in[20];
    const float* fb1   = (const float*)d_in[21];
    const float* fw2   = (const float*)d_in[22];
    const float* fb2   = (const float*)d_in[23];
    const float* fw3   = (const float*)d_in[24];
    const float* fb3   = (const float*)d_in[25];
    float* out = (float*)d_out;

    prep_transpose<<<256, 256>>>(w_ih);
    prep_WT2<<<128, 256>>>(mr, mi);
    gemm_X<<<dim3(8, 16), 128>>>(word, lut, b_ih, b_hh);
    lstm_kernel<<<64, 256>>>(w_hh);
    combine_kernel<<<BS, 128>>>(word, audio, ph0, ph1, w_lin, b_lin,
                                w1, b1, w2, b2, w3, b3, modw);
    gemm_M<<<dim3(8, 16), 128>>>();
    pool_mlp<<<32, 128>>>(fw1, fb1, fw2, fb2, fw3, fb3, out);
}